// round 4
// baseline (speedup 1.0000x reference)
#include <cuda_runtime.h>
#include <math.h>

#define N_NODES 50000
#define N_EDGES 640000
#define F 128
#define HID 128
#define NLAY 3
#define NG 256
#define NC 10
#define NB_SCAN 196   // ceil(50000/256)

// ----------------- persistent device scratch -----------------
__device__ float d_x[N_NODES * F];       // current node features
__device__ float d_h[N_NODES * F];       // GEMM output
__device__ float d_att[N_NODES];
__device__ float d_dinv[N_NODES];
__device__ int   d_degin[N_NODES];
__device__ int   d_rowptr[N_NODES + 1];
__device__ int   d_fillpos[N_NODES];
__device__ int   d_col[N_EDGES];
__device__ float d_ecoef[N_EDGES];
__device__ float d_bnsum[F];
__device__ float d_bnsqs[F];
__device__ float d_bna[F];
__device__ float d_bnb[F];
__device__ int   d_gstart[NG + 1];
__device__ float d_grep[NG * 3 * HID];
__device__ int   d_bsums[256];

// ----------------- zero init -----------------
__global__ void k_zero() {
    int i = blockIdx.x * blockDim.x + threadIdx.x;   // grid covers 98304
    if (i < NG * 3 * HID) d_grep[i] = 0.f;
    if (i < N_NODES) d_degin[i] = 0;
    if (i < F) { d_bnsum[i] = 0.f; d_bnsqs[i] = 0.f; }
}

// ----------------- batchnorm -----------------
__global__ void k_bnstats(const float* __restrict__ x) {
    int f = threadIdx.x;             // 128 threads
    float s = 0.f, s2 = 0.f;
    for (int r = blockIdx.x; r < N_NODES; r += gridDim.x) {
        float v = x[r * F + f];
        s += v; s2 += v * v;
    }
    atomicAdd(&d_bnsum[f], s);
    atomicAdd(&d_bnsqs[f], s2);
}

__global__ void k_bncoef(const float* __restrict__ gamma, const float* __restrict__ beta) {
    int t = threadIdx.x;
    float mean = d_bnsum[t] / (float)N_NODES;
    float var  = d_bnsqs[t] / (float)N_NODES - mean * mean;
    float a = gamma[t] / sqrtf(var + 1e-5f);
    d_bna[t] = a;
    d_bnb[t] = beta[t] - mean * a;
}

__global__ void k_bnapply(const float* __restrict__ xin) {
    const int n4 = N_NODES * F / 4;
    for (int i = blockIdx.x * blockDim.x + threadIdx.x; i < n4; i += gridDim.x * blockDim.x) {
        int f4 = (i & 31) * 4;
        float4 v = ((const float4*)xin)[i];
        v.x = v.x * d_bna[f4 + 0] + d_bnb[f4 + 0];
        v.y = v.y * d_bna[f4 + 1] + d_bnb[f4 + 1];
        v.z = v.z * d_bna[f4 + 2] + d_bnb[f4 + 2];
        v.w = v.w * d_bna[f4 + 3] + d_bnb[f4 + 3];
        ((float4*)d_x)[i] = v;
    }
}

// ----------------- degree / CSR build -----------------
__global__ void k_deg(const int* __restrict__ ei) {
    int e = blockIdx.x * blockDim.x + threadIdx.x;
    if (e >= N_EDGES) return;
    int s = ei[e], d = ei[N_EDGES + e];
    if (s != d) atomicAdd(&d_degin[d], 1);
}

__global__ void k_dinv() {
    int i = blockIdx.x * blockDim.x + threadIdx.x;
    if (i < N_NODES) d_dinv[i] = 1.0f / sqrtf((float)(d_degin[i] + 1));
}

__global__ void k_scan1() {
    __shared__ int sh[256];
    int t = threadIdx.x;
    int i = blockIdx.x * 256 + t;
    int v = (i < N_NODES) ? d_degin[i] : 0;
    sh[t] = v; __syncthreads();
#pragma unroll
    for (int off = 1; off < 256; off <<= 1) {
        int u = (t >= off) ? sh[t - off] : 0;
        __syncthreads();
        sh[t] += u;
        __syncthreads();
    }
    if (i < N_NODES) d_rowptr[i] = sh[t] - v;      // block-local exclusive
    if (t == 255) d_bsums[blockIdx.x] = sh[255];
}

__global__ void k_scan2() {
    __shared__ int sh[256];
    int t = threadIdx.x;
    int v = (t < NB_SCAN) ? d_bsums[t] : 0;
    sh[t] = v; __syncthreads();
#pragma unroll
    for (int off = 1; off < 256; off <<= 1) {
        int u = (t >= off) ? sh[t - off] : 0;
        __syncthreads();
        sh[t] += u;
        __syncthreads();
    }
    if (t < NB_SCAN) d_bsums[t] = sh[t] - v;       // exclusive block offsets
}

__global__ void k_scan3() {
    int i = blockIdx.x * 256 + threadIdx.x;
    if (i < N_NODES) {
        int r = d_rowptr[i] + d_bsums[i >> 8];
        d_rowptr[i] = r;
        d_fillpos[i] = r;
        if (i == N_NODES - 1) d_rowptr[N_NODES] = r + d_degin[i];
    }
}

__global__ void k_fill(const int* __restrict__ ei) {
    int e = blockIdx.x * blockDim.x + threadIdx.x;
    if (e >= N_EDGES) return;
    int s = ei[e], d = ei[N_EDGES + e];
    if (s != d) {
        int p = atomicAdd(&d_fillpos[d], 1);
        d_col[p] = s;
        d_ecoef[p] = d_dinv[s] * d_dinv[d];
    }
}

// ----------------- per-graph node ranges -----------------
__global__ void k_gstart(const int* __restrict__ batch) {
    int t = threadIdx.x;
    if (t > NG) return;
    int lo = 0, hi = N_NODES;
    while (lo < hi) {
        int mid = (lo + hi) >> 1;
        if (batch[mid] < t) lo = mid + 1; else hi = mid;
    }
    d_gstart[t] = lo;
}

// ----------------- GEMM: d_h = d_x @ W  (N x 128 @ 128 x 128) -----------------
__global__ __launch_bounds__(256, 2) void k_gemm(const float* __restrict__ W) {
    __shared__ float As[32][68];     // [k][m], padded; 16B-aligned rows (68*4=272)
    __shared__ float Ws[32][128];    // [k][n]
    int tid = threadIdx.x;
    int m0 = blockIdx.x * 64;
    int tr = tid >> 4, tc = tid & 15;

    float acc[4][8];
#pragma unroll
    for (int i = 0; i < 4; i++)
#pragma unroll
        for (int j = 0; j < 8; j++) acc[i][j] = 0.f;

    for (int kc = 0; kc < 128; kc += 32) {
        // load A tile 64x32 (2 passes of 32 rows)
#pragma unroll
        for (int p = 0; p < 2; p++) {
            int row = p * 32 + (tid >> 3);
            int kq = (tid & 7) * 4;
            float4 v = make_float4(0.f, 0.f, 0.f, 0.f);
            int m = m0 + row;
            if (m < N_NODES) v = *(const float4*)&d_x[m * 128 + kc + kq];
            As[kq + 0][row] = v.x;
            As[kq + 1][row] = v.y;
            As[kq + 2][row] = v.z;
            As[kq + 3][row] = v.w;
        }
        // load W tile 32x128 (4 passes of 8 rows)
#pragma unroll
        for (int p = 0; p < 4; p++) {
            int kr = p * 8 + (tid >> 5);
            int nc = (tid & 31) * 4;
            *(float4*)&Ws[kr][nc] = *(const float4*)&W[(kc + kr) * 128 + nc];
        }
        __syncthreads();
#pragma unroll
        for (int k = 0; k < 32; k++) {
            float4 a  = *(float4*)&As[k][tr * 4];
            float4 b0 = *(float4*)&Ws[k][tc * 8];
            float4 b1 = *(float4*)&Ws[k][tc * 8 + 4];
            float av[4] = {a.x, a.y, a.z, a.w};
            float bv[8] = {b0.x, b0.y, b0.z, b0.w, b1.x, b1.y, b1.z, b1.w};
#pragma unroll
            for (int i = 0; i < 4; i++)
#pragma unroll
                for (int j = 0; j < 8; j++) acc[i][j] += av[i] * bv[j];
        }
        __syncthreads();
    }
#pragma unroll
    for (int i = 0; i < 4; i++) {
        int m = m0 + tr * 4 + i;
        if (m < N_NODES) {
            float4 o0 = make_float4(acc[i][0], acc[i][1], acc[i][2], acc[i][3]);
            float4 o1 = make_float4(acc[i][4], acc[i][5], acc[i][6], acc[i][7]);
            *(float4*)&d_h[m * 128 + tc * 8]     = o0;
            *(float4*)&d_h[m * 128 + tc * 8 + 4] = o1;
        }
    }
}

// -------- aggregate (gather CSR) + bias + squash + attention dot; warp per node --------
__global__ __launch_bounds__(256) void k_agg(const float* __restrict__ bias,
                                             const float* __restrict__ watt) {
    int gw = (blockIdx.x * blockDim.x + threadIdx.x) >> 5;
    if (gw >= N_NODES) return;
    int lane = threadIdx.x & 31;
    int v = gw;

    const float4* h4 = (const float4*)d_h;
    float dv = d_dinv[v];
    float sc = dv * dv;
    float4 hv = h4[v * 32 + lane];
    float4 acc = make_float4(sc * hv.x, sc * hv.y, sc * hv.z, sc * hv.w);

    int beg = d_rowptr[v], end = d_rowptr[v + 1];
    for (int p = beg; p < end; p++) {
        int s = d_col[p];
        float c = d_ecoef[p];
        float4 hs = h4[s * 32 + lane];
        acc.x += c * hs.x; acc.y += c * hs.y; acc.z += c * hs.z; acc.w += c * hs.w;
    }
    float4 b = ((const float4*)bias)[lane];
    acc.x += b.x; acc.y += b.y; acc.z += b.z; acc.w += b.w;

    // squash
    float n2 = acc.x * acc.x + acc.y * acc.y + acc.z * acc.z + acc.w * acc.w;
#pragma unroll
    for (int o = 16; o; o >>= 1) n2 += __shfl_xor_sync(0xffffffffu, n2, o);
    float s2 = n2 / ((1.f + n2) * sqrtf(n2 + 1e-8f));
    float4 xo = make_float4(s2 * acc.x, s2 * acc.y, s2 * acc.z, s2 * acc.w);
    ((float4*)d_x)[v * 32 + lane] = xo;

    // attention score
    float4 wa = ((const float4*)watt)[lane];
    float ap = xo.x * wa.x + xo.y * wa.y + xo.z * wa.z + xo.w * wa.w;
#pragma unroll
    for (int o = 16; o; o >>= 1) ap += __shfl_xor_sync(0xffffffffu, ap, o);
    if (lane == 0) d_att[v] = ap;
}

// ----------------- per-graph readout (block per graph) -----------------
__global__ void k_readout() {
    int g = blockIdx.x;
    int t = threadIdx.x;       // 128
    int s0 = d_gstart[g], s1 = d_gstart[g + 1];
    float ws = 0.f, sm = 0.f, mx = -INFINITY;
    for (int v = s0; v < s1; v++) {
        float val = d_x[v * F + t];
        float a = d_att[v];
        ws += a * val;
        sm += val;
        mx = fmaxf(mx, val);
    }
    float cnt = fmaxf(1.f, (float)(s1 - s0));
    if (s1 == s0) mx = 0.f;
    d_grep[g * 384 + t]       += ws;
    d_grep[g * 384 + 128 + t] += sm / cnt;
    d_grep[g * 384 + 256 + t] += mx;
}

// ----------------- final MLP + log_softmax -----------------
__global__ void k_mlp(const float* __restrict__ w1, const float* __restrict__ b1,
                      const float* __restrict__ w2, const float* __restrict__ b2,
                      float* __restrict__ out) {
    int g = blockIdx.x;
    int t = threadIdx.x;    // 128
    __shared__ float rep[384];
    __shared__ float h1[128];
    __shared__ float logits[NC];
    rep[t]       = d_grep[g * 384 + t];
    rep[t + 128] = d_grep[g * 384 + 128 + t];
    rep[t + 256] = d_grep[g * 384 + 256 + t];
    __syncthreads();
    float acc = b1[t];
    for (int k = 0; k < 384; k++) acc += rep[k] * w1[k * 128 + t];
    h1[t] = fmaxf(acc, 0.f);
    __syncthreads();
    if (t < NC) {
        float a = b2[t];
        for (int k = 0; k < 128; k++) a += h1[k] * w2[k * NC + t];
        logits[t] = a;
    }
    __syncthreads();
    if (t == 0) {
        float m = -INFINITY;
        for (int c = 0; c < NC; c++) m = fmaxf(m, logits[c]);
        float se = 0.f;
        for (int c = 0; c < NC; c++) se += expf(logits[c] - m);
        float lse = m + logf(se);
        for (int c = 0; c < NC; c++) out[g * NC + c] = logits[c] - lse;
    }
}

// ----------------- launch -----------------
extern "C" void kernel_launch(void* const* d_in, const int* in_sizes, int n_in,
                              void* d_out, int out_size) {
    const float* x      = (const float*)d_in[0];
    const int*   ei     = (const int*)d_in[1];     // [2, E] int32 (JAX x64 disabled)
    const int*   batch  = (const int*)d_in[2];     // [N] int32, sorted
    const float* gamma  = (const float*)d_in[3];
    const float* beta   = (const float*)d_in[4];
    const float* gcn_w  = (const float*)d_in[5];   // [3,128,128]
    const float* gcn_b  = (const float*)d_in[6];   // [3,128]
    const float* w_att  = (const float*)d_in[7];   // [3,128]
    const float* lin1_w = (const float*)d_in[8];   // [384,128]
    const float* lin1_b = (const float*)d_in[9];
    const float* lin2_w = (const float*)d_in[10];  // [128,10]
    const float* lin2_b = (const float*)d_in[11];
    float* out = (float*)d_out;

    k_zero<<<96, 1024>>>();
    k_bnstats<<<256, 128>>>(x);
    k_bncoef<<<1, 128>>>(gamma, beta);
    k_bnapply<<<640, 256>>>(x);
    k_deg<<<(N_EDGES + 255) / 256, 256>>>(ei);
    k_dinv<<<NB_SCAN, 256>>>();
    k_scan1<<<NB_SCAN, 256>>>();
    k_scan2<<<1, 256>>>();
    k_scan3<<<NB_SCAN, 256>>>();
    k_fill<<<(N_EDGES + 255) / 256, 256>>>(ei);
    k_gstart<<<1, 512>>>(batch);

    for (int l = 0; l < NLAY; l++) {
        k_gemm<<<(N_NODES + 63) / 64, 256>>>(gcn_w + l * 128 * 128);
        k_agg<<<(N_NODES * 32 + 255) / 256, 256>>>(gcn_b + l * 128, w_att + l * 128);
        k_readout<<<NG, 128>>>();
    }
    k_mlp<<<NG, 128>>>(lin1_w, lin1_b, lin2_w, lin2_b, out);
}

// round 8
// speedup vs baseline: 1.3244x; 1.3244x over previous
#include <cuda_runtime.h>
#include <cuda_bf16.h>
#include <math.h>
#include <stdint.h>

#define N_NODES 50000
#define N_EDGES 640000
#define F 128
#define HID 128
#define NLAY 3
#define NG 256
#define NC 10
#define NB_SCAN 196   // ceil(50000/256)

#define PAD 136                        // smem row stride in bf16 elems (272B)
#define TILE_ELEMS (128 * PAD)         // 17408 elems = 34816 B
#define SM_GEMM_BYTES (4 * TILE_ELEMS * 2)   // 139264 B

// ----------------- persistent device scratch -----------------
__device__ float d_x[N_NODES * F];       // current node features
__device__ float d_h[N_NODES * F];       // GEMM output, pre-scaled by dinv (h')
__device__ float d_att[N_NODES];
__device__ float d_dinv[N_NODES];
__device__ int   d_degin[N_NODES];
__device__ int   d_rowptr[N_NODES + 1];
__device__ int   d_fillpos[N_NODES];
__device__ int   d_col[N_EDGES];
__device__ float d_bnsum[F];
__device__ float d_bnsqs[F];
__device__ float d_bna[F];
__device__ float d_bnb[F];
__device__ int   d_gstart[NG + 1];
__device__ float d_grep[NG * 3 * HID];
__device__ int   d_bsums[256];
// split-bf16 weights, transposed: [layer][n*128 + k],  B[n][k] = W[k][n]
__device__ unsigned short d_whi[NLAY][16384];
__device__ unsigned short d_wlo[NLAY][16384];

// ----------------- zero init -----------------
__global__ void k_zero() {
    int i = blockIdx.x * blockDim.x + threadIdx.x;   // grid covers 98304
    if (i < NG * 3 * HID) d_grep[i] = 0.f;
    if (i < N_NODES) d_degin[i] = 0;
    if (i < F) { d_bnsum[i] = 0.f; d_bnsqs[i] = 0.f; }
}

// ----------------- batchnorm -----------------
__global__ void k_bnstats(const float* __restrict__ x) {
    int f = threadIdx.x;             // 128 threads
    float s = 0.f, s2 = 0.f;
    for (int r = blockIdx.x; r < N_NODES; r += gridDim.x) {
        float v = x[r * F + f];
        s += v; s2 += v * v;
    }
    atomicAdd(&d_bnsum[f], s);
    atomicAdd(&d_bnsqs[f], s2);
}

__global__ void k_bncoef(const float* __restrict__ gamma, const float* __restrict__ beta) {
    int t = threadIdx.x;
    float mean = d_bnsum[t] / (float)N_NODES;
    float var  = d_bnsqs[t] / (float)N_NODES - mean * mean;
    float a = gamma[t] / sqrtf(var + 1e-5f);
    d_bna[t] = a;
    d_bnb[t] = beta[t] - mean * a;
}

__global__ void k_bnapply(const float* __restrict__ xin) {
    int lane = threadIdx.x & 31;
    int w  = (blockIdx.x * blockDim.x + threadIdx.x) >> 5;
    int nw = (gridDim.x * blockDim.x) >> 5;
    float4 a = *(const float4*)&d_bna[lane * 4];
    float4 b = *(const float4*)&d_bnb[lane * 4];
    for (int r = w; r < N_NODES; r += nw) {
        float4 v = ((const float4*)xin)[r * 32 + lane];
        v.x = fmaf(v.x, a.x, b.x);
        v.y = fmaf(v.y, a.y, b.y);
        v.z = fmaf(v.z, a.z, b.z);
        v.w = fmaf(v.w, a.w, b.w);
        ((float4*)d_x)[r * 32 + lane] = v;
    }
}

// ----------------- degree / CSR build -----------------
__global__ void k_deg(const int* __restrict__ ei) {
    int e = blockIdx.x * blockDim.x + threadIdx.x;
    if (e >= N_EDGES) return;
    int s = ei[e], d = ei[N_EDGES + e];
    if (s != d) atomicAdd(&d_degin[d], 1);
}

__global__ void k_dinv() {
    int i = blockIdx.x * blockDim.x + threadIdx.x;
    if (i < N_NODES) d_dinv[i] = 1.0f / sqrtf((float)(d_degin[i] + 1));
}

__global__ void k_scan1() {
    __shared__ int sh[256];
    int t = threadIdx.x;
    int i = blockIdx.x * 256 + t;
    int v = (i < N_NODES) ? d_degin[i] : 0;
    sh[t] = v; __syncthreads();
#pragma unroll
    for (int off = 1; off < 256; off <<= 1) {
        int u = (t >= off) ? sh[t - off] : 0;
        __syncthreads();
        sh[t] += u;
        __syncthreads();
    }
    if (i < N_NODES) d_rowptr[i] = sh[t] - v;      // block-local exclusive
    if (t == 255) d_bsums[blockIdx.x] = sh[255];
}

__global__ void k_scan2() {
    __shared__ int sh[256];
    int t = threadIdx.x;
    int v = (t < NB_SCAN) ? d_bsums[t] : 0;
    sh[t] = v; __syncthreads();
#pragma unroll
    for (int off = 1; off < 256; off <<= 1) {
        int u = (t >= off) ? sh[t - off] : 0;
        __syncthreads();
        sh[t] += u;
        __syncthreads();
    }
    if (t < NB_SCAN) d_bsums[t] = sh[t] - v;       // exclusive block offsets
}

__global__ void k_scan3() {
    int i = blockIdx.x * 256 + threadIdx.x;
    if (i < N_NODES) {
        int r = d_rowptr[i] + d_bsums[i >> 8];
        d_rowptr[i] = r;
        d_fillpos[i] = r;
        if (i == N_NODES - 1) d_rowptr[N_NODES] = r + d_degin[i];
    }
}

__global__ void k_fill(const int* __restrict__ ei) {
    int e = blockIdx.x * blockDim.x + threadIdx.x;
    if (e >= N_EDGES) return;
    int s = ei[e], d = ei[N_EDGES + e];
    if (s != d) {
        int p = atomicAdd(&d_fillpos[d], 1);
        d_col[p] = s;
    }
}

// ----------------- per-graph node ranges -----------------
__global__ void k_gstart(const int* __restrict__ batch) {
    int t = threadIdx.x;
    if (t > NG) return;
    int lo = 0, hi = N_NODES;
    while (lo < hi) {
        int mid = (lo + hi) >> 1;
        if (batch[mid] < t) lo = mid + 1; else hi = mid;
    }
    d_gstart[t] = lo;
}

// ----------------- split-bf16 weight prep: B[n][k] = W[k][n] -----------------
__global__ void k_prepw(const float* __restrict__ gw) {
    int l = blockIdx.x;
    for (int idx = threadIdx.x; idx < 16384; idx += blockDim.x) {
        int n = idx >> 7, k = idx & 127;
        float w = gw[l * 16384 + k * 128 + n];
        __nv_bfloat16 hi = __float2bfloat16(w);
        __nv_bfloat16 lo = __float2bfloat16(w - __bfloat162float(hi));
        d_whi[l][n * 128 + k] = __bfloat16_as_ushort(hi);
        d_wlo[l][n * 128 + k] = __bfloat16_as_ushort(lo);
    }
}

// ----------------- mma.sync helpers -----------------
__device__ __forceinline__ void ldsm_x4(uint32_t* r, uint32_t addr) {
    asm volatile("ldmatrix.sync.aligned.m8n8.x4.shared.b16 {%0,%1,%2,%3}, [%4];"
        : "=r"(r[0]), "=r"(r[1]), "=r"(r[2]), "=r"(r[3]) : "r"(addr));
}
__device__ __forceinline__ void ldsm_x2(uint32_t* r, uint32_t addr) {
    asm volatile("ldmatrix.sync.aligned.m8n8.x2.shared.b16 {%0,%1}, [%2];"
        : "=r"(r[0]), "=r"(r[1]) : "r"(addr));
}
__device__ __forceinline__ void mma_bf16(float* c, const uint32_t* a, const uint32_t* b) {
    asm volatile("mma.sync.aligned.m16n8k16.row.col.f32.bf16.bf16.f32 "
        "{%0,%1,%2,%3}, {%4,%5,%6,%7}, {%8,%9}, {%0,%1,%2,%3};"
        : "+f"(c[0]), "+f"(c[1]), "+f"(c[2]), "+f"(c[3])
        : "r"(a[0]), "r"(a[1]), "r"(a[2]), "r"(a[3]), "r"(b[0]), "r"(b[1]));
}

// D[m][n] = sum_k x[m][k]*W[k][n], 3-pass split bf16: Ahi*Bhi + Ahi*Blo + Alo*Bhi.
// Epilogue writes h' = dinv[m] * h[m].
__global__ __launch_bounds__(256, 1) void k_gemm_mma(int layer) {
    extern __shared__ unsigned short smem[];
    unsigned short* As_hi = smem;
    unsigned short* As_lo = smem + TILE_ELEMS;
    unsigned short* Bs_hi = smem + 2 * TILE_ELEMS;
    unsigned short* Bs_lo = smem + 3 * TILE_ELEMS;
    const uint32_t OFF_ALO = TILE_ELEMS * 2;      // byte offsets between buffers
    const uint32_t OFF_B   = 2 * TILE_ELEMS * 2;

    int tid = threadIdx.x, wid = tid >> 5, lane = tid & 31;
    int m0 = blockIdx.x * 128;

    // copy pre-split B tiles, rows n (stride 128 elems) -> smem stride PAD
    {
        const uint4* sh = (const uint4*)d_whi[layer];
        const uint4* sl = (const uint4*)d_wlo[layer];
        for (int i = tid; i < 2048; i += 256) {        // 2048 uint4 = 16K elems
            int n = i >> 4, q = i & 15;                // 16 uint4 per row
            ((uint4*)Bs_hi)[n * 17 + q] = sh[i];       // PAD=136 elems = 17 uint4
            ((uint4*)Bs_lo)[n * 17 + q] = sl[i];
        }
    }
    // load A rows, split fp32 -> bf16 hi/lo
    for (int idx = tid; idx < 8192; idx += 256) {      // 8192 float2 = 128x128
        int row = idx >> 6, k = (idx & 63) * 2;
        int m = m0 + row;
        float2 v = make_float2(0.f, 0.f);
        if (m < N_NODES) v = *(const float2*)&d_x[m * 128 + k];
        __nv_bfloat16 h0 = __float2bfloat16(v.x);
        __nv_bfloat16 h1 = __float2bfloat16(v.y);
        __nv_bfloat16 l0 = __float2bfloat16(v.x - __bfloat162float(h0));
        __nv_bfloat16 l1 = __float2bfloat16(v.y - __bfloat162float(h1));
        uint32_t hp = (uint32_t)__bfloat16_as_ushort(h0) | ((uint32_t)__bfloat16_as_ushort(h1) << 16);
        uint32_t lp = (uint32_t)__bfloat16_as_ushort(l0) | ((uint32_t)__bfloat16_as_ushort(l1) << 16);
        *(uint32_t*)(As_hi + row * PAD + k) = hp;
        *(uint32_t*)(As_lo + row * PAD + k) = lp;
    }
    __syncthreads();

    int mw = (wid & 3) * 32;        // warp tile: 32 rows x 64 cols
    int nw = (wid >> 2) * 64;

    float c[2][8][4];
#pragma unroll
    for (int i = 0; i < 2; i++)
#pragma unroll
        for (int j = 0; j < 8; j++)
#pragma unroll
            for (int q = 0; q < 4; q++) c[i][j][q] = 0.f;

    uint32_t sbase = (uint32_t)__cvta_generic_to_shared(smem);
    int la = lane & 15, lah = lane >> 4;      // A ldmatrix lane mapping
    int lb = lane & 7,  lbh = (lane >> 3) & 1;  // B ldmatrix lane mapping (x2: lanes 0-15)

#pragma unroll
    for (int ks = 0; ks < 8; ks++) {
        int kb = ks * 16;
        uint32_t ahi[2][4], alo[2][4];
#pragma unroll
        for (int i = 0; i < 2; i++) {
            uint32_t addr = sbase + (uint32_t)(((mw + i * 16 + la) * PAD + kb + lah * 8) * 2);
            ldsm_x4(ahi[i], addr);
            ldsm_x4(alo[i], addr + OFF_ALO);
        }
        uint32_t bhi[8][2], blo[8][2];
#pragma unroll
        for (int j = 0; j < 8; j++) {
            uint32_t addr = sbase + OFF_B + (uint32_t)(((nw + j * 8 + lb) * PAD + kb + lbh * 8) * 2);
            ldsm_x2(bhi[j], addr);
            ldsm_x2(blo[j], addr + OFF_ALO);
        }
        // pass 1: Ahi*Bhi (16 independent mmas)
#pragma unroll
        for (int j = 0; j < 8; j++)
#pragma unroll
            for (int i = 0; i < 2; i++) mma_bf16(c[i][j], ahi[i], bhi[j]);
        // pass 2: Ahi*Blo
#pragma unroll
        for (int j = 0; j < 8; j++)
#pragma unroll
            for (int i = 0; i < 2; i++) mma_bf16(c[i][j], ahi[i], blo[j]);
        // pass 3: Alo*Bhi
#pragma unroll
        for (int j = 0; j < 8; j++)
#pragma unroll
            for (int i = 0; i < 2; i++) mma_bf16(c[i][j], alo[i], bhi[j]);
    }

    // epilogue: scale by dinv[m], write d_h
    int group = lane >> 2, qp = lane & 3;
#pragma unroll
    for (int i = 0; i < 2; i++) {
        int r0 = m0 + mw + i * 16 + group;
        int r1 = r0 + 8;
        float dv0 = (r0 < N_NODES) ? d_dinv[r0] : 0.f;
        float dv1 = (r1 < N_NODES) ? d_dinv[r1] : 0.f;
#pragma unroll
        for (int j = 0; j < 8; j++) {
            int col = nw + j * 8 + qp * 2;
            if (r0 < N_NODES) {
                float2 o0 = make_float2(c[i][j][0] * dv0, c[i][j][1] * dv0);
                *(float2*)&d_h[r0 * 128 + col] = o0;
            }
            if (r1 < N_NODES) {
                float2 o1 = make_float2(c[i][j][2] * dv1, c[i][j][3] * dv1);
                *(float2*)&d_h[r1 * 128 + col] = o1;
            }
        }
    }
}

// -------- aggregate (gather CSR on h' = dinv*h) + bias + squash + att; warp/node ----
__global__ __launch_bounds__(256) void k_agg(const float* __restrict__ bias,
                                             const float* __restrict__ watt) {
    int v = (blockIdx.x * blockDim.x + threadIdx.x) >> 5;
    if (v >= N_NODES) return;
    int lane = threadIdx.x & 31;

    const float4* h4 = (const float4*)d_h;
    float4 acc = h4[v * 32 + lane];            // self term h'[v]
    int beg = d_rowptr[v], end = d_rowptr[v + 1];
    for (int p = beg; p < end; p++) {
        int s = d_col[p];
        float4 hs = h4[s * 32 + lane];
        acc.x += hs.x; acc.y += hs.y; acc.z += hs.z; acc.w += hs.w;
    }
    float dv = d_dinv[v];
    float4 b = ((const float4*)bias)[lane];
    acc.x = fmaf(acc.x, dv, b.x);
    acc.y = fmaf(acc.y, dv, b.y);
    acc.z = fmaf(acc.z, dv, b.z);
    acc.w = fmaf(acc.w, dv, b.w);

    // squash
    float n2 = acc.x * acc.x + acc.y * acc.y + acc.z * acc.z + acc.w * acc.w;
#pragma unroll
    for (int o = 16; o; o >>= 1) n2 += __shfl_xor_sync(0xffffffffu, n2, o);
    float s2 = n2 / ((1.f + n2) * sqrtf(n2 + 1e-8f));
    float4 xo = make_float4(s2 * acc.x, s2 * acc.y, s2 * acc.z, s2 * acc.w);
    ((float4*)d_x)[v * 32 + lane] = xo;

    // attention score
    float4 wa = ((const float4*)watt)[lane];
    float ap = xo.x * wa.x + xo.y * wa.y + xo.z * wa.z + xo.w * wa.w;
#pragma unroll
    for (int o = 16; o; o >>= 1) ap += __shfl_xor_sync(0xffffffffu, ap, o);
    if (lane == 0) d_att[v] = ap;
}

// ----------------- per-graph readout (block per graph) -----------------
__global__ void k_readout() {
    int g = blockIdx.x;
    int t = threadIdx.x;       // 128
    int s0 = d_gstart[g], s1 = d_gstart[g + 1];
    float ws = 0.f, sm = 0.f, mx = -INFINITY;
    for (int v = s0; v < s1; v++) {
        float val = d_x[v * F + t];
        float a = d_att[v];
        ws += a * val;
        sm += val;
        mx = fmaxf(mx, val);
    }
    float cnt = fmaxf(1.f, (float)(s1 - s0));
    if (s1 == s0) mx = 0.f;
    d_grep[g * 384 + t]       += ws;
    d_grep[g * 384 + 128 + t] += sm / cnt;
    d_grep[g * 384 + 256 + t] += mx;
}

// ----------------- final MLP + log_softmax -----------------
__global__ void k_mlp(const float* __restrict__ w1, const float* __restrict__ b1,
                      const float* __restrict__ w2, const float* __restrict__ b2,
                      float* __restrict__ out) {
    int g = blockIdx.x;
    int t = threadIdx.x;    // 128
    __shared__ float rep[384];
    __shared__ float h1[128];
    __shared__ float logits[NC];
    rep[t]       = d_grep[g * 384 + t];
    rep[t + 128] = d_grep[g * 384 + 128 + t];
    rep[t + 256] = d_grep[g * 384 + 256 + t];
    __syncthreads();
    float acc = b1[t];
    for (int k = 0; k < 384; k++) acc += rep[k] * w1[k * 128 + t];
    h1[t] = fmaxf(acc, 0.f);
    __syncthreads();
    if (t < NC) {
        float a = b2[t];
        for (int k = 0; k < 128; k++) a += h1[k] * w2[k * NC + t];
        logits[t] = a;
    }
    __syncthreads();
    if (t == 0) {
        float m = -INFINITY;
        for (int c = 0; c < NC; c++) m = fmaxf(m, logits[c]);
        float se = 0.f;
        for (int c = 0; c < NC; c++) se += expf(logits[c] - m);
        float lse = m + logf(se);
        for (int c = 0; c < NC; c++) out[g * NC + c] = logits[c] - lse;
    }
}

// ----------------- launch -----------------
extern "C" void kernel_launch(void* const* d_in, const int* in_sizes, int n_in,
                              void* d_out, int out_size) {
    const float* x      = (const float*)d_in[0];
    const int*   ei     = (const int*)d_in[1];     // [2, E] int32
    const int*   batch  = (const int*)d_in[2];     // [N] int32, sorted
    const float* gamma  = (const float*)d_in[3];
    const float* beta   = (const float*)d_in[4];
    const float* gcn_w  = (const float*)d_in[5];   // [3,128,128]
    const float* gcn_b  = (const float*)d_in[6];   // [3,128]
    const float* w_att  = (const float*)d_in[7];   // [3,128]
    const float* lin1_w = (const float*)d_in[8];   // [384,128]
    const float* lin1_b = (const float*)d_in[9];
    const float* lin2_w = (const float*)d_in[10];  // [128,10]
    const float* lin2_b = (const float*)d_in[11];
    float* out = (float*)d_out;

    cudaFuncSetAttribute(k_gemm_mma, cudaFuncAttributeMaxDynamicSharedMemorySize,
                         SM_GEMM_BYTES);

    k_zero<<<96, 1024>>>();
    k_bnstats<<<256, 128>>>(x);
    k_bncoef<<<1, 128>>>(gamma, beta);
    k_bnapply<<<512, 256>>>(x);
    k_deg<<<(N_EDGES + 255) / 256, 256>>>(ei);
    k_dinv<<<NB_SCAN, 256>>>();
    k_scan1<<<NB_SCAN, 256>>>();
    k_scan2<<<1, 256>>>();
    k_scan3<<<NB_SCAN, 256>>>();
    k_fill<<<(N_EDGES + 255) / 256, 256>>>(ei);
    k_gstart<<<1, 512>>>(batch);
    k_prepw<<<NLAY, 256>>>(gcn_w);

    for (int l = 0; l < NLAY; l++) {
        k_gemm_mma<<<(N_NODES + 127) / 128, 256, SM_GEMM_BYTES>>>(l);
        k_agg<<<(N_NODES * 32 + 255) / 256, 256>>>(gcn_b + l * 128, w_att + l * 128);
        k_readout<<<NG, 128>>>();
    }
    k_mlp<<<NG, 128>>>(lin1_w, lin1_b, lin2_w, lin2_b, out);
}

// round 11
// speedup vs baseline: 1.6715x; 1.2621x over previous
#include <cuda_runtime.h>
#include <cuda_bf16.h>
#include <math.h>
#include <stdint.h>

#define N_NODES 50000
#define N_EDGES 640000
#define F 128
#define HID 128
#define NLAY 3
#define NG 256
#define NC 10
#define NB_SCAN 196   // ceil(50000/256)

#define PAD 136                        // smem row stride in bf16 elems (272B)
#define TILE_ELEMS (128 * PAD)         // 17408 elems = 34816 B
#define SM_GEMM_BYTES (4 * TILE_ELEMS * 2)   // 139264 B

#define ENC_NEG_INF 0x007FFFFFu

// ----------------- persistent device scratch -----------------
__device__ float d_x[N_NODES * F];       // current node features
__device__ float d_h[N_NODES * F];       // GEMM output, pre-scaled by dinv (h')
__device__ float d_att[N_NODES];
__device__ float d_dinv[N_NODES];
__device__ int   d_degin[N_NODES];
__device__ int   d_rowptr[N_NODES + 1];
__device__ int   d_fillpos[N_NODES];
__device__ int   d_col[N_EDGES];
__device__ float d_bnsum[F];
__device__ float d_bnsqs[F];
__device__ float d_bna[F];
__device__ float d_bnb[F];
__device__ int   d_gstart[NG + 1];
__device__ int   d_bsums[256];
// readout accumulators
__device__ float d_gws[NG * HID];            // sum over layers of att-weighted sum
__device__ float d_gsum[NG * HID];           // sum over layers of plain sum
__device__ unsigned d_gmaxu[NLAY][NG * HID]; // per-layer max, order-encoded
// split-bf16 weights, transposed: [layer][n*128 + k],  B[n][k] = W[k][n]
__device__ unsigned short d_whi[NLAY][16384];
__device__ unsigned short d_wlo[NLAY][16384];

// order-preserving float <-> uint encode for atomicMax
__device__ __forceinline__ unsigned encf(float f) {
    unsigned u = __float_as_uint(f);
    return (u & 0x80000000u) ? ~u : (u | 0x80000000u);
}
__device__ __forceinline__ float decf(unsigned e) {
    unsigned u = (e & 0x80000000u) ? (e & 0x7FFFFFFFu) : ~e;
    return __uint_as_float(u);
}

// ----------------- zero init -----------------
__global__ void k_zero() {
    int i = blockIdx.x * blockDim.x + threadIdx.x;   // grid covers 98304
    if (i < NLAY * NG * HID) ((unsigned*)d_gmaxu)[i] = ENC_NEG_INF;
    if (i < NG * HID) { d_gws[i] = 0.f; d_gsum[i] = 0.f; }
    if (i < N_NODES) d_degin[i] = 0;
    if (i < F) { d_bnsum[i] = 0.f; d_bnsqs[i] = 0.f; }
}

// ----------------- batchnorm stats -----------------
__global__ void k_bnstats(const float* __restrict__ x) {
    int f = threadIdx.x;             // 128 threads
    float s = 0.f, s2 = 0.f;
    for (int r = blockIdx.x; r < N_NODES; r += gridDim.x) {
        float v = x[r * F + f];
        s += v; s2 += v * v;
    }
    atomicAdd(&d_bnsum[f], s);
    atomicAdd(&d_bnsqs[f], s2);
}

__global__ void k_bncoef(const float* __restrict__ gamma, const float* __restrict__ beta) {
    int t = threadIdx.x;
    float mean = d_bnsum[t] / (float)N_NODES;
    float var  = d_bnsqs[t] / (float)N_NODES - mean * mean;
    float a = gamma[t] / sqrtf(var + 1e-5f);
    d_bna[t] = a;
    d_bnb[t] = beta[t] - mean * a;
}

// ----------------- degree / CSR build -----------------
__global__ void k_deg(const int* __restrict__ ei) {
    int e = blockIdx.x * blockDim.x + threadIdx.x;
    if (e >= N_EDGES) return;
    int s = ei[e], d = ei[N_EDGES + e];
    if (s != d) atomicAdd(&d_degin[d], 1);
}

__global__ void k_scan1() {
    __shared__ int sh[256];
    int t = threadIdx.x;
    int i = blockIdx.x * 256 + t;
    int v = (i < N_NODES) ? d_degin[i] : 0;
    if (i < N_NODES) d_dinv[i] = rsqrtf((float)(v + 1));   // fused dinv
    sh[t] = v; __syncthreads();
#pragma unroll
    for (int off = 1; off < 256; off <<= 1) {
        int u = (t >= off) ? sh[t - off] : 0;
        __syncthreads();
        sh[t] += u;
        __syncthreads();
    }
    if (i < N_NODES) d_rowptr[i] = sh[t] - v;      // block-local exclusive
    if (t == 255) d_bsums[blockIdx.x] = sh[255];
}

__global__ void k_scan2() {
    __shared__ int sh[256];
    int t = threadIdx.x;
    int v = (t < NB_SCAN) ? d_bsums[t] : 0;
    sh[t] = v; __syncthreads();
#pragma unroll
    for (int off = 1; off < 256; off <<= 1) {
        int u = (t >= off) ? sh[t - off] : 0;
        __syncthreads();
        sh[t] += u;
        __syncthreads();
    }
    if (t < NB_SCAN) d_bsums[t] = sh[t] - v;       // exclusive block offsets
}

__global__ void k_scan3() {
    int i = blockIdx.x * 256 + threadIdx.x;
    if (i < N_NODES) {
        int r = d_rowptr[i] + d_bsums[i >> 8];
        d_rowptr[i] = r;
        d_fillpos[i] = r;
        if (i == N_NODES - 1) d_rowptr[N_NODES] = r + d_degin[i];
    }
}

__global__ void k_fill(const int* __restrict__ ei) {
    int e = blockIdx.x * blockDim.x + threadIdx.x;
    if (e >= N_EDGES) return;
    int s = ei[e], d = ei[N_EDGES + e];
    if (s != d) {
        int p = atomicAdd(&d_fillpos[d], 1);
        d_col[p] = s;
    }
}

// ----------------- per-graph node ranges -----------------
__global__ void k_gstart(const int* __restrict__ batch) {
    int t = threadIdx.x;
    if (t > NG) return;
    int lo = 0, hi = N_NODES;
    while (lo < hi) {
        int mid = (lo + hi) >> 1;
        if (batch[mid] < t) lo = mid + 1; else hi = mid;
    }
    d_gstart[t] = lo;
}

// ----------------- split-bf16 weight prep: B[n][k] = W[k][n] -----------------
__global__ void k_prepw(const float* __restrict__ gw) {
    int l = blockIdx.x;
    for (int idx = threadIdx.x; idx < 16384; idx += blockDim.x) {
        int n = idx >> 7, k = idx & 127;
        float w = gw[l * 16384 + k * 128 + n];
        __nv_bfloat16 hi = __float2bfloat16(w);
        __nv_bfloat16 lo = __float2bfloat16(w - __bfloat162float(hi));
        d_whi[l][n * 128 + k] = __bfloat16_as_ushort(hi);
        d_wlo[l][n * 128 + k] = __bfloat16_as_ushort(lo);
    }
}

// ----------------- mma.sync helpers -----------------
__device__ __forceinline__ void ldsm_x4(uint32_t* r, uint32_t addr) {
    asm volatile("ldmatrix.sync.aligned.m8n8.x4.shared.b16 {%0,%1,%2,%3}, [%4];"
        : "=r"(r[0]), "=r"(r[1]), "=r"(r[2]), "=r"(r[3]) : "r"(addr));
}
__device__ __forceinline__ void ldsm_x2(uint32_t* r, uint32_t addr) {
    asm volatile("ldmatrix.sync.aligned.m8n8.x2.shared.b16 {%0,%1}, [%2];"
        : "=r"(r[0]), "=r"(r[1]) : "r"(addr));
}
__device__ __forceinline__ void mma_bf16(float* c, const uint32_t* a, const uint32_t* b) {
    asm volatile("mma.sync.aligned.m16n8k16.row.col.f32.bf16.bf16.f32 "
        "{%0,%1,%2,%3}, {%4,%5,%6,%7}, {%8,%9}, {%0,%1,%2,%3};"
        : "+f"(c[0]), "+f"(c[1]), "+f"(c[2]), "+f"(c[3])
        : "r"(a[0]), "r"(a[1]), "r"(a[2]), "r"(a[3]), "r"(b[0]), "r"(b[1]));
}

// D[m][n] = sum_k A[m][k]*W[k][n], 3-pass split bf16: Ahi*Bhi + Ahi*Blo + Alo*Bhi.
// A = xsrc (optionally BN-transformed on load). Epilogue writes h' = dinv[m]*h[m].
__global__ __launch_bounds__(256, 1) void k_gemm_mma(int layer,
                                                     const float* __restrict__ xsrc,
                                                     int apply_bn) {
    extern __shared__ unsigned short smem[];
    unsigned short* As_hi = smem;
    unsigned short* As_lo = smem + TILE_ELEMS;
    unsigned short* Bs_hi = smem + 2 * TILE_ELEMS;
    unsigned short* Bs_lo = smem + 3 * TILE_ELEMS;
    const uint32_t OFF_ALO = TILE_ELEMS * 2;      // byte offsets between buffers
    const uint32_t OFF_B   = 2 * TILE_ELEMS * 2;

    int tid = threadIdx.x, wid = tid >> 5, lane = tid & 31;
    int m0 = blockIdx.x * 128;

    // copy pre-split B tiles, rows n (stride 128 elems) -> smem stride PAD
    {
        const uint4* sh = (const uint4*)d_whi[layer];
        const uint4* sl = (const uint4*)d_wlo[layer];
        for (int i = tid; i < 2048; i += 256) {        // 2048 uint4 = 16K elems
            int n = i >> 4, q = i & 15;                // 16 uint4 per row
            ((uint4*)Bs_hi)[n * 17 + q] = sh[i];       // PAD=136 elems = 17 uint4
            ((uint4*)Bs_lo)[n * 17 + q] = sl[i];
        }
    }
    // load A rows (fused BN for layer 0), split fp32 -> bf16 hi/lo
    for (int idx = tid; idx < 8192; idx += 256) {      // 8192 float2 = 128x128
        int row = idx >> 6, k = (idx & 63) * 2;
        int m = m0 + row;
        float2 v = make_float2(0.f, 0.f);
        if (m < N_NODES) v = *(const float2*)&xsrc[m * 128 + k];
        if (apply_bn) {
            float2 a = *(const float2*)&d_bna[k];
            float2 b = *(const float2*)&d_bnb[k];
            v.x = fmaf(v.x, a.x, b.x);
            v.y = fmaf(v.y, a.y, b.y);
        }
        __nv_bfloat16 h0 = __float2bfloat16(v.x);
        __nv_bfloat16 h1 = __float2bfloat16(v.y);
        __nv_bfloat16 l0 = __float2bfloat16(v.x - __bfloat162float(h0));
        __nv_bfloat16 l1 = __float2bfloat16(v.y - __bfloat162float(h1));
        uint32_t hp = (uint32_t)__bfloat16_as_ushort(h0) | ((uint32_t)__bfloat16_as_ushort(h1) << 16);
        uint32_t lp = (uint32_t)__bfloat16_as_ushort(l0) | ((uint32_t)__bfloat16_as_ushort(l1) << 16);
        *(uint32_t*)(As_hi + row * PAD + k) = hp;
        *(uint32_t*)(As_lo + row * PAD + k) = lp;
    }
    __syncthreads();

    int mw = (wid & 3) * 32;        // warp tile: 32 rows x 64 cols
    int nw = (wid >> 2) * 64;

    float c[2][8][4];
#pragma unroll
    for (int i = 0; i < 2; i++)
#pragma unroll
        for (int j = 0; j < 8; j++)
#pragma unroll
            for (int q = 0; q < 4; q++) c[i][j][q] = 0.f;

    uint32_t sbase = (uint32_t)__cvta_generic_to_shared(smem);
    int la = lane & 15, lah = lane >> 4;        // A ldmatrix lane mapping
    int lb = lane & 7,  lbh = (lane >> 3) & 1;  // B ldmatrix lane mapping (x2: lanes 0-15)

#pragma unroll
    for (int ks = 0; ks < 8; ks++) {
        int kb = ks * 16;
        uint32_t ahi[2][4], alo[2][4];
#pragma unroll
        for (int i = 0; i < 2; i++) {
            uint32_t addr = sbase + (uint32_t)(((mw + i * 16 + la) * PAD + kb + lah * 8) * 2);
            ldsm_x4(ahi[i], addr);
            ldsm_x4(alo[i], addr + OFF_ALO);
        }
        uint32_t bhi[8][2], blo[8][2];
#pragma unroll
        for (int j = 0; j < 8; j++) {
            uint32_t addr = sbase + OFF_B + (uint32_t)(((nw + j * 8 + lb) * PAD + kb + lbh * 8) * 2);
            ldsm_x2(bhi[j], addr);
            ldsm_x2(blo[j], addr + OFF_ALO);
        }
#pragma unroll
        for (int j = 0; j < 8; j++)
#pragma unroll
            for (int i = 0; i < 2; i++) mma_bf16(c[i][j], ahi[i], bhi[j]);
#pragma unroll
        for (int j = 0; j < 8; j++)
#pragma unroll
            for (int i = 0; i < 2; i++) mma_bf16(c[i][j], ahi[i], blo[j]);
#pragma unroll
        for (int j = 0; j < 8; j++)
#pragma unroll
            for (int i = 0; i < 2; i++) mma_bf16(c[i][j], alo[i], bhi[j]);
    }

    // epilogue: scale by dinv[m], write d_h
    int group = lane >> 2, qp = lane & 3;
#pragma unroll
    for (int i = 0; i < 2; i++) {
        int r0 = m0 + mw + i * 16 + group;
        int r1 = r0 + 8;
        float dv0 = (r0 < N_NODES) ? d_dinv[r0] : 0.f;
        float dv1 = (r1 < N_NODES) ? d_dinv[r1] : 0.f;
#pragma unroll
        for (int j = 0; j < 8; j++) {
            int col = nw + j * 8 + qp * 2;
            if (r0 < N_NODES) {
                float2 o0 = make_float2(c[i][j][0] * dv0, c[i][j][1] * dv0);
                *(float2*)&d_h[r0 * 128 + col] = o0;
            }
            if (r1 < N_NODES) {
                float2 o1 = make_float2(c[i][j][2] * dv1, c[i][j][3] * dv1);
                *(float2*)&d_h[r1 * 128 + col] = o1;
            }
        }
    }
}

// -------- aggregate (gather CSR on h' = dinv*h) + bias + squash + att; warp/node ----
__global__ __launch_bounds__(256) void k_agg(const float* __restrict__ bias,
                                             const float* __restrict__ watt) {
    int v = (blockIdx.x * blockDim.x + threadIdx.x) >> 5;
    if (v >= N_NODES) return;
    int lane = threadIdx.x & 31;

    const float4* h4 = (const float4*)d_h;
    float4 acc = h4[v * 32 + lane];            // self term h'[v]
    int beg = d_rowptr[v], end = d_rowptr[v + 1];
    for (int p = beg; p < end; p++) {
        int s = d_col[p];
        float4 hs = h4[s * 32 + lane];
        acc.x += hs.x; acc.y += hs.y; acc.z += hs.z; acc.w += hs.w;
    }
    float dv = d_dinv[v];
    float4 b = ((const float4*)bias)[lane];
    acc.x = fmaf(acc.x, dv, b.x);
    acc.y = fmaf(acc.y, dv, b.y);
    acc.z = fmaf(acc.z, dv, b.z);
    acc.w = fmaf(acc.w, dv, b.w);

    // squash
    float n2 = acc.x * acc.x + acc.y * acc.y + acc.z * acc.z + acc.w * acc.w;
#pragma unroll
    for (int o = 16; o; o >>= 1) n2 += __shfl_xor_sync(0xffffffffu, n2, o);
    float s2 = n2 / ((1.f + n2) * sqrtf(n2 + 1e-8f));
    float4 xo = make_float4(s2 * acc.x, s2 * acc.y, s2 * acc.z, s2 * acc.w);
    ((float4*)d_x)[v * 32 + lane] = xo;

    // attention score
    float4 wa = ((const float4*)watt)[lane];
    float ap = xo.x * wa.x + xo.y * wa.y + xo.z * wa.z + xo.w * wa.w;
#pragma unroll
    for (int o = 16; o; o >>= 1) ap += __shfl_xor_sync(0xffffffffu, ap, o);
    if (lane == 0) d_att[v] = ap;
}

// --------- per-graph readout, 4 slices per graph, atomic combine ---------
__global__ void k_readout4(int layer) {
    int g = blockIdx.x >> 2, sl = blockIdx.x & 3;
    int t = threadIdx.x;       // 128
    int s0 = d_gstart[g], s1 = d_gstart[g + 1], len = s1 - s0;
    int a0 = s0 + ((len * sl) >> 2);
    int a1 = s0 + ((len * (sl + 1)) >> 2);
    if (a1 <= a0) return;
    float ws = 0.f, sm = 0.f, mx = -INFINITY;
    for (int v = a0; v < a1; v++) {
        float val = d_x[v * F + t];
        float a = d_att[v];
        ws += a * val;
        sm += val;
        mx = fmaxf(mx, val);
    }
    atomicAdd(&d_gws[g * HID + t], ws);
    atomicAdd(&d_gsum[g * HID + t], sm);
    atomicMax(&d_gmaxu[layer][g * HID + t], encf(mx));
}

// ----------------- final MLP + log_softmax -----------------
__global__ void k_mlp(const float* __restrict__ w1, const float* __restrict__ b1,
                      const float* __restrict__ w2, const float* __restrict__ b2,
                      float* __restrict__ out) {
    int g = blockIdx.x;
    int t = threadIdx.x;    // 128
    __shared__ float rep[384];
    __shared__ float h1[128];
    __shared__ float logits[NC];
    float cnt = fmaxf(1.f, (float)(d_gstart[g + 1] - d_gstart[g]));
    rep[t]       = d_gws[g * HID + t];
    rep[t + 128] = d_gsum[g * HID + t] / cnt;
    float mxs = 0.f;
#pragma unroll
    for (int l = 0; l < NLAY; l++) {
        float m = decf(d_gmaxu[l][g * HID + t]);
        if (isfinite(m)) mxs += m;
    }
    rep[t + 256] = mxs;
    __syncthreads();
    float acc = b1[t];
    for (int k = 0; k < 384; k++) acc += rep[k] * w1[k * 128 + t];
    h1[t] = fmaxf(acc, 0.f);
    __syncthreads();
    if (t < NC) {
        float a = b2[t];
        for (int k = 0; k < 128; k++) a += h1[k] * w2[k * NC + t];
        logits[t] = a;
    }
    __syncthreads();
    if (t == 0) {
        float m = -INFINITY;
        for (int c = 0; c < NC; c++) m = fmaxf(m, logits[c]);
        float se = 0.f;
        for (int c = 0; c < NC; c++) se += expf(logits[c] - m);
        float lse = m + logf(se);
        for (int c = 0; c < NC; c++) out[g * NC + c] = logits[c] - lse;
    }
}

// ----------------- launch -----------------
extern "C" void kernel_launch(void* const* d_in, const int* in_sizes, int n_in,
                              void* d_out, int out_size) {
    const float* x      = (const float*)d_in[0];
    const int*   ei     = (const int*)d_in[1];     // [2, E] int32
    const int*   batch  = (const int*)d_in[2];     // [N] int32, sorted
    const float* gamma  = (const float*)d_in[3];
    const float* beta   = (const float*)d_in[4];
    const float* gcn_w  = (const float*)d_in[5];   // [3,128,128]
    const float* gcn_b  = (const float*)d_in[6];   // [3,128]
    const float* w_att  = (const float*)d_in[7];   // [3,128]
    const float* lin1_w = (const float*)d_in[8];   // [384,128]
    const float* lin1_b = (const float*)d_in[9];
    const float* lin2_w = (const float*)d_in[10];  // [128,10]
    const float* lin2_b = (const float*)d_in[11];
    float* out = (float*)d_out;

    cudaFuncSetAttribute(k_gemm_mma, cudaFuncAttributeMaxDynamicSharedMemorySize,
                         SM_GEMM_BYTES);

    // d_x device pointer for layers 1,2 A source
    float* d_x_ptr = nullptr;
    cudaGetSymbolAddress((void**)&d_x_ptr, d_x);

    k_zero<<<96, 1024>>>();
    k_bnstats<<<512, 128>>>(x);
    k_bncoef<<<1, 128>>>(gamma, beta);
    k_deg<<<(N_EDGES + 255) / 256, 256>>>(ei);
    k_scan1<<<NB_SCAN, 256>>>();
    k_scan2<<<1, 256>>>();
    k_scan3<<<NB_SCAN, 256>>>();
    k_fill<<<(N_EDGES + 255) / 256, 256>>>(ei);
    k_gstart<<<1, 512>>>(batch);
    k_prepw<<<NLAY, 256>>>(gcn_w);

    for (int l = 0; l < NLAY; l++) {
        const float* xsrc = (l == 0) ? x : (const float*)d_x_ptr;
        k_gemm_mma<<<(N_NODES + 127) / 128, 256, SM_GEMM_BYTES>>>(l, xsrc, l == 0 ? 1 : 0);
        k_agg<<<(N_NODES * 32 + 255) / 256, 256>>>(gcn_b + l * 128, w_att + l * 128);
        k_readout4<<<NG * 4, 128>>>(l);
    }
    k_mlp<<<NG, 128>>>(lin1_w, lin1_b, lin2_w, lin2_b, out);
}